// round 13
// baseline (speedup 1.0000x reference)
#include <cuda_runtime.h>
#include <cuda_fp16.h>
#include <cstdint>

// ---------------- problem constants ----------------
#define L     3072
#define NTOK  3071
#define Dm    512
#define Hh    8
#define DHd   64
#define T_TYPES 15
#define N_ARGS  73
#define N_MAPS  3
#define TQ    4            // query rows per attention block

typedef __half f16;

// ---------------- scratch (static device globals; no allocations) ----------------
__device__ float g_qkv[L * 3 * Dm];
__device__ float g_a [L * Dm];
__device__ float g_xa[L * Dm];
__device__ float g_y [L * Dm];
__device__ float g_bqkv[3 * Dm];
__device__ float g_etab[(T_TYPES + N_ARGS + N_MAPS) * Dm];   // 91 x 512
__device__ int   g_seg[L];

// fp16 hi/lo planes for activations; weights hi-only
__device__ f16 g_xh [L * Dm];  __device__ f16 g_xl [L * Dm];
__device__ f16 g_oh [L * Dm];  __device__ f16 g_ol [L * Dm];
__device__ f16 g_xah[L * Dm];  __device__ f16 g_xal[L * Dm];
__device__ f16 g_hh [L * Dm];  __device__ f16 g_hl [L * Dm];
__device__ f16 g_Wh[6 * Dm * Dm];   // Wq,Wk,Wv | Wo | W1 | W2 (hi plane)

// ---------------- helpers ----------------
__device__ __forceinline__ void split_f16(float x, f16& h, f16& l) {
    h = __float2half_rn(x);
    l = __float2half_rn(x - __half2float(h));
}
__device__ __forceinline__ void cp16(uint32_t dst, const void* src) {
    asm volatile("cp.async.cg.shared.global [%0], [%1], 16;\n" :: "r"(dst), "l"(src));
}
__device__ __forceinline__ void ldsm4(uint32_t* r, uint32_t addr) {
    asm volatile("ldmatrix.sync.aligned.m8n8.x4.shared.b16 {%0,%1,%2,%3}, [%4];\n"
                 : "=r"(r[0]), "=r"(r[1]), "=r"(r[2]), "=r"(r[3]) : "r"(addr));
}
__device__ __forceinline__ void mma_f16(float* d, const uint32_t* a, uint32_t b0, uint32_t b1) {
    asm volatile(
        "mma.sync.aligned.m16n8k16.row.col.f32.f16.f16.f32 "
        "{%0,%1,%2,%3}, {%4,%5,%6,%7}, {%8,%9}, {%0,%1,%2,%3};\n"
        : "+f"(d[0]), "+f"(d[1]), "+f"(d[2]), "+f"(d[3])
        : "r"(a[0]), "r"(a[1]), "r"(a[2]), "r"(a[3]), "r"(b0), "r"(b1));
}

// ================= prep mega-kernel: scan | conv6 | pretab =================
#define ETAB_N ((T_TYPES + N_ARGS + N_MAPS) * Dm)   // 46592
#define PREP_CONV0 1
#define PREP_TAB0  385
#define PREP_BLKS  433

__global__ __launch_bounds__(1024) void prep_kernel(
    const int* __restrict__ seq, int* __restrict__ segOut,
    const float* __restrict__ Wq, const float* __restrict__ Wk,
    const float* __restrict__ Wv, const float* __restrict__ Wo,
    const float* __restrict__ W1, const float* __restrict__ W2,
    f16* __restrict__ hi,
    const float* __restrict__ Wt, const float* __restrict__ bt,
    const float* __restrict__ Wa, const float* __restrict__ ba,
    const float* __restrict__ Wm, const float* __restrict__ bm,
    const float* __restrict__ bq, const float* __restrict__ bk,
    const float* __restrict__ bv,
    float* __restrict__ Et, float* __restrict__ bqkv)
{
    const int b = blockIdx.x;
    const int tid = threadIdx.x;

    if (b == 0) {
        __shared__ int sM[L];
        __shared__ int warpAgg[32];
        int lane = tid & 31, wid = tid >> 5;
        int k0 = tid * 3;
        int v0 = (k0     < NTOK && seq[k0]     == 0) ? k0 + 1 : 0;
        int v1 = (k0 + 1 < NTOK && seq[k0 + 1] == 0) ? k0 + 2 : 0;
        int v2 = (k0 + 2 < NTOK && seq[k0 + 2] == 0) ? k0 + 3 : 0;
        int m1 = max(v0, v1), m2 = max(m1, v2);
        int x = m2;
#pragma unroll
        for (int off = 1; off < 32; off <<= 1) {
            int y = __shfl_up_sync(0xffffffffu, x, off);
            if (lane >= off) x = max(x, y);
        }
        if (lane == 31) warpAgg[wid] = x;
        int exw = __shfl_up_sync(0xffffffffu, x, 1);
        if (lane == 0) exw = 0;
        __syncthreads();
        if (wid == 0) {
            int w = warpAgg[lane];
#pragma unroll
            for (int off = 1; off < 32; off <<= 1) {
                int y = __shfl_up_sync(0xffffffffu, w, off);
                if (lane >= off) w = max(w, y);
            }
            int ex = __shfl_up_sync(0xffffffffu, w, 1);
            if (lane == 0) ex = 0;
            warpAgg[lane] = ex;
        }
        __syncthreads();
        int base = max(warpAgg[wid], exw);
        sM[k0]     = max(base, v0);
        sM[k0 + 1] = max(base, m1);
        sM[k0 + 2] = max(base, m2);
        __syncthreads();
        if (tid == 0) segOut[0] = 0;
#pragma unroll
        for (int u = 1; u <= 3; ++u) {
            int i = k0 + u;
            if (i < L) segOut[i] = max(1, sM[i - 1]);
        }
    } else if (b < PREP_TAB0) {
        int bb = b - PREP_CONV0;
        int wsel = bb >> 6;
        int i = (bb & 63) * 1024 + tid;
        const float* in = (wsel == 0) ? Wq : (wsel == 1) ? Wk : (wsel == 2) ? Wv
                        : (wsel == 3) ? Wo : (wsel == 4) ? W1 : W2;
        size_t basew = (size_t)wsel * Dm * Dm;
        float4 xv = ((const float4*)in)[i];
        __half2 p0, p1;
        p0.x = __float2half_rn(xv.x); p0.y = __float2half_rn(xv.y);
        p1.x = __float2half_rn(xv.z); p1.y = __float2half_rn(xv.w);
        __half2* H = (__half2*)(hi + basew);
        H[i * 2 + 0] = p0;
        H[i * 2 + 1] = p1;
    } else {
        int i = (b - PREP_TAB0) * 1024 + tid;
        if (i < ETAB_N) {
            int r = i >> 9, d = i & 511;
            float v;
            if (r < T_TYPES)               v = Wt[d * T_TYPES + r] + bt[d];
            else if (r < T_TYPES + N_ARGS) v = Wa[d * N_ARGS + (r - T_TYPES)] + ba[d];
            else                           v = Wm[d * N_MAPS + (r - T_TYPES - N_ARGS)] + bm[d];
            Et[i] = v;
        } else if (i < ETAB_N + 3 * Dm) {
            int j = i - ETAB_N;
            const float* src = (j < Dm) ? bq : (j < 2 * Dm) ? bk : bv;
            bqkv[j] = src[j & (Dm - 1)];
        }
    }
}

// ---------------- embedding ----------------
__global__ __launch_bounds__(128) void embed_kernel(const int* __restrict__ idx,
                              const float* __restrict__ Et, const float* __restrict__ sos,
                              f16* __restrict__ Xh, f16* __restrict__ Xl) {
    int n = blockIdx.x;
    int tid = threadIdx.x;
    int c = tid * 4;
    float4 v;
    if (n == 0) {
        v = *(const float4*)(sos + c);
    } else {
        int id = idx[n - 1];
        int t = id / (N_ARGS * N_MAPS);
        int a = (id / N_MAPS) % N_ARGS;
        int m = id % N_MAPS;
        float4 vt = *(const float4*)(Et + (size_t)t * Dm + c);
        float4 va = *(const float4*)(Et + (size_t)(T_TYPES + a) * Dm + c);
        float4 vm = *(const float4*)(Et + (size_t)(T_TYPES + N_ARGS + m) * Dm + c);
        v.x = vt.x + va.x + vm.x;
        v.y = vt.y + va.y + vm.y;
        v.z = vt.z + va.z + vm.z;
        v.w = vt.w + va.w + vm.w;
    }
    f16 h0, l0, h1, l1, h2, l2, h3, l3;
    split_f16(v.x, h0, l0); split_f16(v.y, h1, l1);
    split_f16(v.z, h2, l2); split_f16(v.w, h3, l3);
    __half2 t2;
    t2.x = h0; t2.y = h1; *(__half2*)(Xh + (size_t)n * Dm + c) = t2;
    t2.x = h2; t2.y = h3; *(__half2*)(Xh + (size_t)n * Dm + c + 2) = t2;
    t2.x = l0; t2.y = l1; *(__half2*)(Xl + (size_t)n * Dm + c) = t2;
    t2.x = l2; t2.y = l3; *(__half2*)(Xl + (size_t)n * Dm + c + 2) = t2;
}

// ---------------- tensor-core GEMM (round-7 3-stage) ----------------
#define STG_A    5120
#define STG_BYTES (3 * STG_A)
#define SMEM_TOT (3 * STG_BYTES)      // 46080

__global__ __launch_bounds__(128) void gemm_f16_kernel(
    const f16* __restrict__ Ah, const f16* __restrict__ Al,
    const f16* __restrict__ Wh,
    const float* __restrict__ bias,
    float* __restrict__ outF,
    f16* __restrict__ outHi, f16* __restrict__ outLo,
    int act, int ldc)
{
    extern __shared__ __align__(16) unsigned char smem_raw[];
    const uint32_t sbase = (uint32_t)__cvta_generic_to_shared(smem_raw);
    const int tid = threadIdx.x;
    const int lane = tid & 31, wid = tid >> 5;
    const int bm = blockIdx.y * 64, bn = blockIdx.x * 64;
    const int warp_m = wid >> 1, warp_n = wid & 1;

    const int lr = tid >> 1;
    const int lhalf = tid & 1;
    const uint32_t sOff = (uint32_t)lr * 80 + lhalf * 32;

    const int a_off = (warp_m * 32 + (lane & 7) + ((lane >> 3) & 1) * 8) * 80
                    + ((lane >> 4) & 1) * 16;
    const int b_off = (warp_n * 32 + (lane & 7) + ((lane >> 4) & 1) * 8) * 80
                    + ((lane >> 3) & 1) * 16;

    const f16* gAh0 = Ah + (size_t)(bm + lr) * Dm + lhalf * 16;
    const f16* gAl0 = Al + (size_t)(bm + lr) * Dm + lhalf * 16;
    const f16* gBh0 = Wh + (size_t)(bn + lr) * Dm + lhalf * 16;

    float acc[2][4][4];
#pragma unroll
    for (int mt = 0; mt < 2; ++mt)
#pragma unroll
        for (int nt = 0; nt < 4; ++nt)
#pragma unroll
            for (int u = 0; u < 4; ++u) acc[mt][nt][u] = 0.f;

#define LOADSTAGE(s, k0) do {                                   \
        uint32_t d0 = sbase + (s) * STG_BYTES + sOff;           \
        cp16(d0,                  gAh0 + (k0));                 \
        cp16(d0 + 16,             gAh0 + (k0) + 8);             \
        cp16(d0 + STG_A,          gAl0 + (k0));                 \
        cp16(d0 + STG_A + 16,     gAl0 + (k0) + 8);             \
        cp16(d0 + 2 * STG_A,      gBh0 + (k0));                 \
        cp16(d0 + 2 * STG_A + 16, gBh0 + (k0) + 8);             \
        asm volatile("cp.async.commit_group;\n" ::);            \
    } while (0)

    LOADSTAGE(0, 0);
    LOADSTAGE(1, 32);

    int sCur = 0, sNxt = 2;
    for (int kt = 0; kt < 16; ++kt) {
        if (kt < 15)
            asm volatile("cp.async.wait_group 1;\n" ::);
        else
            asm volatile("cp.async.wait_group 0;\n" ::);
        __syncthreads();

        const uint32_t sA0 = sbase + sCur * STG_BYTES + a_off;
        const uint32_t sB0 = sbase + sCur * STG_BYTES + 2 * STG_A + b_off;
#pragma unroll
        for (int ks = 0; ks < 2; ++ks) {
            uint32_t ah[2][4], al[2][4], bh[2][4];
#pragma unroll
            for (int mt = 0; mt < 2; ++mt) {
                uint32_t ad = sA0 + mt * 16 * 80 + ks * 32;
                ldsm4(ah[mt], ad);
                ldsm4(al[mt], ad + STG_A);
            }
#pragma unroll
            for (int ng = 0; ng < 2; ++ng) {
                uint32_t bd = sB0 + ng * 16 * 80 + ks * 32;
                ldsm4(bh[ng], bd);
            }
#pragma unroll
            for (int mt = 0; mt < 2; ++mt)
#pragma unroll
                for (int nt = 0; nt < 4; ++nt) {
                    const int ng = nt >> 1, hb = (nt & 1) * 2;
                    mma_f16(acc[mt][nt], ah[mt], bh[ng][hb], bh[ng][hb + 1]);
                    mma_f16(acc[mt][nt], al[mt], bh[ng][hb], bh[ng][hb + 1]);
                }
        }
        if (kt < 14)
            LOADSTAGE(sNxt, (kt + 2) * 32);
        sCur = (sCur == 2) ? 0 : sCur + 1;
        sNxt = (sNxt == 2) ? 0 : sNxt + 1;
    }
#undef LOADSTAGE

    const int gid = lane >> 2, tig = lane & 3;
#pragma unroll
    for (int mt = 0; mt < 2; ++mt)
#pragma unroll
        for (int nt = 0; nt < 4; ++nt) {
            int row = bm + warp_m * 32 + mt * 16 + gid;
            int col = bn + warp_n * 32 + nt * 8 + tig * 2;
            float b0 = bias[col], b1 = bias[col + 1];
            float r0 = acc[mt][nt][0] + b0;
            float r1 = acc[mt][nt][1] + b1;
            float r2 = acc[mt][nt][2] + b0;
            float r3 = acc[mt][nt][3] + b1;
            if (act) {
                r0 = r0 > 0.f ? r0 : 0.01f * r0;
                r1 = r1 > 0.f ? r1 : 0.01f * r1;
                r2 = r2 > 0.f ? r2 : 0.01f * r2;
                r3 = r3 > 0.f ? r3 : 0.01f * r3;
            }
            if (outF) {
                *(float2*)(outF + (size_t)row * ldc + col)       = make_float2(r0, r1);
                *(float2*)(outF + (size_t)(row + 8) * ldc + col) = make_float2(r2, r3);
            }
            if (outHi) {
                f16 h0, l0, h1, l1, h2, l2, h3, l3;
                split_f16(r0, h0, l0); split_f16(r1, h1, l1);
                split_f16(r2, h2, l2); split_f16(r3, h3, l3);
                __half2 t;
                t.x = h0; t.y = h1;
                *(__half2*)(outHi + (size_t)row * ldc + col) = t;
                t.x = l0; t.y = l1;
                *(__half2*)(outLo + (size_t)row * ldc + col) = t;
                t.x = h2; t.y = h3;
                *(__half2*)(outHi + (size_t)(row + 8) * ldc + col) = t;
                t.x = l2; t.y = l3;
                *(__half2*)(outLo + (size_t)(row + 8) * ldc + col) = t;
            }
        }
}

// ---------------- sparse masked attention v4: TQ=4 rows/block, low-reg ----------------
// Same sharing as v3 but: limited unrolls (4 LDG in flight), chunk w/j staged in
// smem (broadcast LDS) instead of per-lane registers + shfl, merged accumulators.
__global__ __launch_bounds__(256, 3) void attn_kernel(
    const float* __restrict__ QKV, const int* __restrict__ seg,
    f16* __restrict__ Oh, f16* __restrict__ Ol) {
    const int i0 = blockIdx.x * TQ;
    const int h = threadIdx.x >> 5;
    const int lane = threadIdx.x & 31;
    __shared__ float qs[TQ][Dm];
    __shared__ float4 swgt[Hh][32];
    __shared__ int   sjj[Hh][32];
    __shared__ int sseg[TQ];

#pragma unroll
    for (int r = 0; r < TQ; ++r)
        for (int c = threadIdx.x; c < Dm; c += 256)
            qs[r][c] = QKV[(size_t)(i0 + r) * 1536 + c];
    if (threadIdx.x < TQ) sseg[threadIdx.x] = seg[i0 + threadIdx.x];
    __syncthreads();

    const int s0 = sseg[0], s1 = sseg[1], s2 = sseg[2], s3 = sseg[3];
    const int smin = s0;                     // seg is non-decreasing
    const int nmax = 1 + max(0, (i0 + 3) - smin);

    const float* Kbase = QKV + Dm;
    const float* Vbase = QKV + 2 * Dm;
    const float* qh0 = qs[0] + h * DHd;
    const float* qh1 = qs[1] + h * DHd;
    const float* qh2 = qs[2] + h * DHd;
    const float* qh3 = qs[3] + h * DHd;

    float m[TQ], l[TQ];
    float2 acc[TQ];
#pragma unroll
    for (int r = 0; r < TQ; ++r) { m[r] = -1e30f; l[r] = 0.f; acc[r] = make_float2(0.f, 0.f); }
    const float* vcol = Vbase + h * DHd + lane * 2;

    for (int base = 0; base < nmax; base += 32) {
        int t = base + lane;
        bool inr = t < nmax;
        int j = (t == 0) ? 0 : smin + t - 1;
        int jc = inr ? j : 0;

        // one K-row read serves 4 dot products; limit unroll -> 4 LDG.128 in flight
        const float4* kr = (const float4*)(Kbase + (size_t)jc * 1536 + h * DHd);
        float d0 = 0.f, d1 = 0.f, d2 = 0.f, d3 = 0.f;
#pragma unroll 4
        for (int c4 = 0; c4 < 16; ++c4) {
            float4 kv = kr[c4];
            float4 q0 = *(const float4*)(qh0 + c4 * 4);
            float4 q1 = *(const float4*)(qh1 + c4 * 4);
            float4 q2 = *(const float4*)(qh2 + c4 * 4);
            float4 q3 = *(const float4*)(qh3 + c4 * 4);
            d0 += q0.x * kv.x + q0.y * kv.y + q0.z * kv.z + q0.w * kv.w;
            d1 += q1.x * kv.x + q1.y * kv.y + q1.z * kv.z + q1.w * kv.w;
            d2 += q2.x * kv.x + q2.y * kv.y + q2.z * kv.z + q2.w * kv.w;
            d3 += q3.x * kv.x + q3.y * kv.y + q3.z * kv.z + q3.w * kv.w;
        }
        bool k0v = (t == 0);
        float sc[TQ];
        sc[0] = (k0v || (inr && j >= s0 && j < i0 + 0)) ? d0 * 0.125f : -1e30f;
        sc[1] = (k0v || (inr && j >= s1 && j < i0 + 1)) ? d1 * 0.125f : -1e30f;
        sc[2] = (k0v || (inr && j >= s2 && j < i0 + 2)) ? d2 * 0.125f : -1e30f;
        sc[3] = (k0v || (inr && j >= s3 && j < i0 + 3)) ? d3 * 0.125f : -1e30f;

        float4 wv4;
        float* wv = (float*)&wv4;
#pragma unroll
        for (int r = 0; r < TQ; ++r) {
            float cm = sc[r];
#pragma unroll
            for (int off = 16; off; off >>= 1)
                cm = fmaxf(cm, __shfl_xor_sync(0xffffffffu, cm, off));
            float nm = fmaxf(m[r], cm);
            float scale = __expf(m[r] - nm);
            float w = (sc[r] > -1e29f) ? __expf(sc[r] - nm) : 0.f;
            float ws = w;
#pragma unroll
            for (int off = 16; off; off >>= 1)
                ws += __shfl_xor_sync(0xffffffffu, ws, off);
            l[r] = l[r] * scale + ws;
            acc[r].x *= scale; acc[r].y *= scale;
            m[r] = nm;
            wv[r] = w;
        }
        swgt[h][lane] = wv4;
        sjj[h][lane] = j;
        __syncwarp();

        int cnt = min(32, nmax - base);
#pragma unroll 4
        for (int t2 = 0; t2 < cnt; ++t2) {
            int jj = sjj[h][t2];
            float4 ww = swgt[h][t2];
            float2 v2 = *(const float2*)(vcol + (size_t)jj * 1536);
            acc[0].x += ww.x * v2.x; acc[0].y += ww.x * v2.y;
            acc[1].x += ww.y * v2.x; acc[1].y += ww.y * v2.y;
            acc[2].x += ww.z * v2.x; acc[2].y += ww.z * v2.y;
            acc[3].x += ww.w * v2.x; acc[3].y += ww.w * v2.y;
        }
        __syncwarp();
    }

    const int col = h * DHd + lane * 2;
#pragma unroll
    for (int r = 0; r < TQ; ++r) {
        float inv = 1.f / l[r];
        float ox = acc[r].x * inv;
        float oy = acc[r].y * inv;
        f16 hx, lx, hy, ly;
        split_f16(ox, hx, lx); split_f16(oy, hy, ly);
        __half2 t2o;
        t2o.x = hx; t2o.y = hy;
        *(__half2*)(Oh + (size_t)(i0 + r) * Dm + col) = t2o;
        t2o.x = lx; t2o.y = ly;
        *(__half2*)(Ol + (size_t)(i0 + r) * Dm + col) = t2o;
    }
}

// ---------------- layernorm ----------------
__global__ __launch_bounds__(128) void ln_kernel(
    const float* __restrict__ X, const float* __restrict__ Y,
    const float* __restrict__ g, const float* __restrict__ b,
    float* __restrict__ outF, f16* __restrict__ outHi, f16* __restrict__ outLo) {
    int row = blockIdx.x;
    int tid = threadIdx.x;
    __shared__ float red[4];
    float v[4];
    float s = 0.f;
#pragma unroll
    for (int u = 0; u < 4; ++u) {
        int c = tid + u * 128;
        float t = X[(size_t)row * Dm + c];
        if (Y) t += Y[(size_t)row * Dm + c];
        v[u] = t; s += t;
    }
#pragma unroll
    for (int off = 16; off; off >>= 1) s += __shfl_xor_sync(0xffffffffu, s, off);
    if ((tid & 31) == 0) red[tid >> 5] = s;
    __syncthreads();
    float mean = (red[0] + red[1] + red[2] + red[3]) * (1.f / 512.f);
    float s2 = 0.f;
#pragma unroll
    for (int u = 0; u < 4; ++u) { float d = v[u] - mean; s2 += d * d; }
#pragma unroll
    for (int off = 16; off; off >>= 1) s2 += __shfl_xor_sync(0xffffffffu, s2, off);
    __syncthreads();
    if ((tid & 31) == 0) red[tid >> 5] = s2;
    __syncthreads();
    float var = (red[0] + red[1] + red[2] + red[3]) * (1.f / 512.f);
    float inv = rsqrtf(var + 1e-5f);
#pragma unroll
    for (int u = 0; u < 4; ++u) {
        int c = tid + u * 128;
        float r = (v[u] - mean) * inv * g[c] + b[c];
        if (outF) outF[(size_t)row * Dm + c] = r;
        if (outHi) {
            f16 h, lo2; split_f16(r, h, lo2);
            outHi[(size_t)row * Dm + c] = h;
            outLo[(size_t)row * Dm + c] = lo2;
        }
    }
}

// ---------------- orchestration ----------------
extern "C" void kernel_launch(void* const* d_in, const int* in_sizes, int n_in,
                              void* d_out, int out_size) {
    const int*   idx = (const int*)d_in[0];
    const int*   seq = (const int*)d_in[1];
    const float* Wt  = (const float*)d_in[2];
    const float* bt  = (const float*)d_in[3];
    const float* Wa  = (const float*)d_in[4];
    const float* ba  = (const float*)d_in[5];
    const float* Wm  = (const float*)d_in[6];
    const float* bm  = (const float*)d_in[7];
    const float* sos = (const float*)d_in[8];
    const float* Wq  = (const float*)d_in[9];
    const float* bq  = (const float*)d_in[10];
    const float* Wk  = (const float*)d_in[11];
    const float* bk  = (const float*)d_in[12];
    const float* Wv  = (const float*)d_in[13];
    const float* bv  = (const float*)d_in[14];
    const float* Wo  = (const float*)d_in[15];
    const float* bo  = (const float*)d_in[16];
    const float* W1  = (const float*)d_in[17];
    const float* b1  = (const float*)d_in[18];
    const float* W2  = (const float*)d_in[19];
    const float* b2  = (const float*)d_in[20];
    const float* g1  = (const float*)d_in[21];
    const float* be1 = (const float*)d_in[22];
    const float* g2  = (const float*)d_in[23];
    const float* be2 = (const float*)d_in[24];
    float* out = (float*)d_out;

    float *qkv, *a, *xa, *y, *bqkv, *etab; int* seg;
    f16 *xh, *xl, *oh, *ol, *xah, *xal, *hh, *hl, *Wbh;
    cudaGetSymbolAddress((void**)&qkv, g_qkv);
    cudaGetSymbolAddress((void**)&a,   g_a);
    cudaGetSymbolAddress((void**)&xa,  g_xa);
    cudaGetSymbolAddress((void**)&y,   g_y);
    cudaGetSymbolAddress((void**)&bqkv, g_bqkv);
    cudaGetSymbolAddress((void**)&etab, g_etab);
    cudaGetSymbolAddress((void**)&seg, g_seg);
    cudaGetSymbolAddress((void**)&xh,  g_xh);
    cudaGetSymbolAddress((void**)&xl,  g_xl);
    cudaGetSymbolAddress((void**)&oh,  g_oh);
    cudaGetSymbolAddress((void**)&ol,  g_ol);
    cudaGetSymbolAddress((void**)&xah, g_xah);
    cudaGetSymbolAddress((void**)&xal, g_xal);
    cudaGetSymbolAddress((void**)&hh,  g_hh);
    cudaGetSymbolAddress((void**)&hl,  g_hl);
    cudaGetSymbolAddress((void**)&Wbh, g_Wh);

    cudaFuncSetAttribute(gemm_f16_kernel,
                         cudaFuncAttributeMaxDynamicSharedMemorySize, SMEM_TOT);

    const size_t WSZ = (size_t)Dm * Dm;

    // launch 1: prep (scan + conv + tables)
    prep_kernel<<<PREP_BLKS, 1024>>>(seq, seg, Wq, Wk, Wv, Wo, W1, W2, Wbh,
                                     Wt, bt, Wa, ba, Wm, bm, bq, bk, bv, etab, bqkv);
    // launch 2: embedding
    embed_kernel<<<L, 128>>>(idx, etab, sos, xh, xl);

    dim3 ggQKV(3 * Dm / 64, L / 64);    // (24, 48)
    dim3 gg(Dm / 64, L / 64);           // (8, 48)
    for (int layer = 0; layer < 2; ++layer) {
        f16* Woh = Wbh + 3 * WSZ;
        f16* W1h = Wbh + 4 * WSZ;
        f16* W2h = Wbh + 5 * WSZ;

        // launch 3: fused QKV GEMM; launch 4 (profiled): attention
        gemm_f16_kernel<<<ggQKV, 128, SMEM_TOT>>>(xh, xl, Wbh, bqkv,
                                                  qkv, nullptr, nullptr, 0, 1536);
        attn_kernel<<<L / TQ, 256>>>(qkv, seg, oh, ol);
        gemm_f16_kernel<<<gg, 128, SMEM_TOT>>>(oh, ol, Woh, bo,
                                               a, nullptr, nullptr, 0, Dm);
        ln_kernel<<<L, 128>>>(a, nullptr, g1, be1, xa, xah, xal);
        gemm_f16_kernel<<<gg, 128, SMEM_TOT>>>(xah, xal, W1h, b1,
                                               nullptr, hh, hl, 1, Dm);
        gemm_f16_kernel<<<gg, 128, SMEM_TOT>>>(hh, hl, W2h, b2,
                                               y, nullptr, nullptr, 0, Dm);
        if (layer == 0)
            ln_kernel<<<L, 128>>>(xa, y, g2, be2, nullptr, xh, xl);
        else
            ln_kernel<<<L, 128>>>(xa, y, g2, be2, out, nullptr, nullptr);
    }
}

// round 14
// speedup vs baseline: 1.6422x; 1.6422x over previous
#include <cuda_runtime.h>
#include <cuda_fp16.h>
#include <cstdint>

// ---------------- problem constants ----------------
#define L     3072
#define NTOK  3071
#define Dm    512
#define Hh    8
#define DHd   64
#define T_TYPES 15
#define N_ARGS  73
#define N_MAPS  3
#define TQ    4            // query rows per attention block
#define KPAD  516          // K-tile smem row stride (floats): 129 16B-units ≡ 1 mod 8

typedef __half f16;

// ---------------- scratch (static device globals; no allocations) ----------------
__device__ float g_qkv[L * 3 * Dm];
__device__ float g_a [L * Dm];
__device__ float g_xa[L * Dm];
__device__ float g_y [L * Dm];
__device__ float g_bqkv[3 * Dm];
__device__ float g_etab[(T_TYPES + N_ARGS + N_MAPS) * Dm];   // 91 x 512
__device__ int   g_seg[L];

// fp16 hi/lo planes for activations; weights hi-only
__device__ f16 g_xh [L * Dm];  __device__ f16 g_xl [L * Dm];
__device__ f16 g_oh [L * Dm];  __device__ f16 g_ol [L * Dm];
__device__ f16 g_xah[L * Dm];  __device__ f16 g_xal[L * Dm];
__device__ f16 g_hh [L * Dm];  __device__ f16 g_hl [L * Dm];
__device__ f16 g_Wh[6 * Dm * Dm];   // Wq,Wk,Wv | Wo | W1 | W2 (hi plane)

// ---------------- helpers ----------------
__device__ __forceinline__ void split_f16(float x, f16& h, f16& l) {
    h = __float2half_rn(x);
    l = __float2half_rn(x - __half2float(h));
}
__device__ __forceinline__ void cp16(uint32_t dst, const void* src) {
    asm volatile("cp.async.cg.shared.global [%0], [%1], 16;\n" :: "r"(dst), "l"(src));
}
__device__ __forceinline__ void ldsm4(uint32_t* r, uint32_t addr) {
    asm volatile("ldmatrix.sync.aligned.m8n8.x4.shared.b16 {%0,%1,%2,%3}, [%4];\n"
                 : "=r"(r[0]), "=r"(r[1]), "=r"(r[2]), "=r"(r[3]) : "r"(addr));
}
__device__ __forceinline__ void mma_f16(float* d, const uint32_t* a, uint32_t b0, uint32_t b1) {
    asm volatile(
        "mma.sync.aligned.m16n8k16.row.col.f32.f16.f16.f32 "
        "{%0,%1,%2,%3}, {%4,%5,%6,%7}, {%8,%9}, {%0,%1,%2,%3};\n"
        : "+f"(d[0]), "+f"(d[1]), "+f"(d[2]), "+f"(d[3])
        : "r"(a[0]), "r"(a[1]), "r"(a[2]), "r"(a[3]), "r"(b0), "r"(b1));
}

// ================= prep mega-kernel: scan | conv6 | pretab =================
#define ETAB_N ((T_TYPES + N_ARGS + N_MAPS) * Dm)   // 46592
#define PREP_CONV0 1
#define PREP_TAB0  385
#define PREP_BLKS  433

__global__ __launch_bounds__(1024) void prep_kernel(
    const int* __restrict__ seq, int* __restrict__ segOut,
    const float* __restrict__ Wq, const float* __restrict__ Wk,
    const float* __restrict__ Wv, const float* __restrict__ Wo,
    const float* __restrict__ W1, const float* __restrict__ W2,
    f16* __restrict__ hi,
    const float* __restrict__ Wt, const float* __restrict__ bt,
    const float* __restrict__ Wa, const float* __restrict__ ba,
    const float* __restrict__ Wm, const float* __restrict__ bm,
    const float* __restrict__ bq, const float* __restrict__ bk,
    const float* __restrict__ bv,
    float* __restrict__ Et, float* __restrict__ bqkv)
{
    const int b = blockIdx.x;
    const int tid = threadIdx.x;

    if (b == 0) {
        __shared__ int sM[L];
        __shared__ int warpAgg[32];
        int lane = tid & 31, wid = tid >> 5;
        int k0 = tid * 3;
        int v0 = (k0     < NTOK && seq[k0]     == 0) ? k0 + 1 : 0;
        int v1 = (k0 + 1 < NTOK && seq[k0 + 1] == 0) ? k0 + 2 : 0;
        int v2 = (k0 + 2 < NTOK && seq[k0 + 2] == 0) ? k0 + 3 : 0;
        int m1 = max(v0, v1), m2 = max(m1, v2);
        int x = m2;
#pragma unroll
        for (int off = 1; off < 32; off <<= 1) {
            int y = __shfl_up_sync(0xffffffffu, x, off);
            if (lane >= off) x = max(x, y);
        }
        if (lane == 31) warpAgg[wid] = x;
        int exw = __shfl_up_sync(0xffffffffu, x, 1);
        if (lane == 0) exw = 0;
        __syncthreads();
        if (wid == 0) {
            int w = warpAgg[lane];
#pragma unroll
            for (int off = 1; off < 32; off <<= 1) {
                int y = __shfl_up_sync(0xffffffffu, w, off);
                if (lane >= off) w = max(w, y);
            }
            int ex = __shfl_up_sync(0xffffffffu, w, 1);
            if (lane == 0) ex = 0;
            warpAgg[lane] = ex;
        }
        __syncthreads();
        int base = max(warpAgg[wid], exw);
        sM[k0]     = max(base, v0);
        sM[k0 + 1] = max(base, m1);
        sM[k0 + 2] = max(base, m2);
        __syncthreads();
        if (tid == 0) segOut[0] = 0;
#pragma unroll
        for (int u = 1; u <= 3; ++u) {
            int i = k0 + u;
            if (i < L) segOut[i] = max(1, sM[i - 1]);
        }
    } else if (b < PREP_TAB0) {
        int bb = b - PREP_CONV0;
        int wsel = bb >> 6;
        int i = (bb & 63) * 1024 + tid;
        const float* in = (wsel == 0) ? Wq : (wsel == 1) ? Wk : (wsel == 2) ? Wv
                        : (wsel == 3) ? Wo : (wsel == 4) ? W1 : W2;
        size_t basew = (size_t)wsel * Dm * Dm;
        float4 xv = ((const float4*)in)[i];
        __half2 p0, p1;
        p0.x = __float2half_rn(xv.x); p0.y = __float2half_rn(xv.y);
        p1.x = __float2half_rn(xv.z); p1.y = __float2half_rn(xv.w);
        __half2* H = (__half2*)(hi + basew);
        H[i * 2 + 0] = p0;
        H[i * 2 + 1] = p1;
    } else {
        int i = (b - PREP_TAB0) * 1024 + tid;
        if (i < ETAB_N) {
            int r = i >> 9, d = i & 511;
            float v;
            if (r < T_TYPES)               v = Wt[d * T_TYPES + r] + bt[d];
            else if (r < T_TYPES + N_ARGS) v = Wa[d * N_ARGS + (r - T_TYPES)] + ba[d];
            else                           v = Wm[d * N_MAPS + (r - T_TYPES - N_ARGS)] + bm[d];
            Et[i] = v;
        } else if (i < ETAB_N + 3 * Dm) {
            int j = i - ETAB_N;
            const float* src = (j < Dm) ? bq : (j < 2 * Dm) ? bk : bv;
            bqkv[j] = src[j & (Dm - 1)];
        }
    }
}

// ---------------- embedding ----------------
__global__ __launch_bounds__(128) void embed_kernel(const int* __restrict__ idx,
                              const float* __restrict__ Et, const float* __restrict__ sos,
                              f16* __restrict__ Xh, f16* __restrict__ Xl) {
    int n = blockIdx.x;
    int tid = threadIdx.x;
    int c = tid * 4;
    float4 v;
    if (n == 0) {
        v = *(const float4*)(sos + c);
    } else {
        int id = idx[n - 1];
        int t = id / (N_ARGS * N_MAPS);
        int a = (id / N_MAPS) % N_ARGS;
        int m = id % N_MAPS;
        float4 vt = *(const float4*)(Et + (size_t)t * Dm + c);
        float4 va = *(const float4*)(Et + (size_t)(T_TYPES + a) * Dm + c);
        float4 vm = *(const float4*)(Et + (size_t)(T_TYPES + N_ARGS + m) * Dm + c);
        v.x = vt.x + va.x + vm.x;
        v.y = vt.y + va.y + vm.y;
        v.z = vt.z + va.z + vm.z;
        v.w = vt.w + va.w + vm.w;
    }
    f16 h0, l0, h1, l1, h2, l2, h3, l3;
    split_f16(v.x, h0, l0); split_f16(v.y, h1, l1);
    split_f16(v.z, h2, l2); split_f16(v.w, h3, l3);
    __half2 t2;
    t2.x = h0; t2.y = h1; *(__half2*)(Xh + (size_t)n * Dm + c) = t2;
    t2.x = h2; t2.y = h3; *(__half2*)(Xh + (size_t)n * Dm + c + 2) = t2;
    t2.x = l0; t2.y = l1; *(__half2*)(Xl + (size_t)n * Dm + c) = t2;
    t2.x = l2; t2.y = l3; *(__half2*)(Xl + (size_t)n * Dm + c + 2) = t2;
}

// ---------------- tensor-core GEMM (round-7 3-stage) ----------------
#define STG_A    5120
#define STG_BYTES (3 * STG_A)
#define SMEM_TOT (3 * STG_BYTES)      // 46080

__global__ __launch_bounds__(128) void gemm_f16_kernel(
    const f16* __restrict__ Ah, const f16* __restrict__ Al,
    const f16* __restrict__ Wh,
    const float* __restrict__ bias,
    float* __restrict__ outF,
    f16* __restrict__ outHi, f16* __restrict__ outLo,
    int act, int ldc)
{
    extern __shared__ __align__(16) unsigned char smem_raw[];
    const uint32_t sbase = (uint32_t)__cvta_generic_to_shared(smem_raw);
    const int tid = threadIdx.x;
    const int lane = tid & 31, wid = tid >> 5;
    const int bm = blockIdx.y * 64, bn = blockIdx.x * 64;
    const int warp_m = wid >> 1, warp_n = wid & 1;

    const int lr = tid >> 1;
    const int lhalf = tid & 1;
    const uint32_t sOff = (uint32_t)lr * 80 + lhalf * 32;

    const int a_off = (warp_m * 32 + (lane & 7) + ((lane >> 3) & 1) * 8) * 80
                    + ((lane >> 4) & 1) * 16;
    const int b_off = (warp_n * 32 + (lane & 7) + ((lane >> 4) & 1) * 8) * 80
                    + ((lane >> 3) & 1) * 16;

    const f16* gAh0 = Ah + (size_t)(bm + lr) * Dm + lhalf * 16;
    const f16* gAl0 = Al + (size_t)(bm + lr) * Dm + lhalf * 16;
    const f16* gBh0 = Wh + (size_t)(bn + lr) * Dm + lhalf * 16;

    float acc[2][4][4];
#pragma unroll
    for (int mt = 0; mt < 2; ++mt)
#pragma unroll
        for (int nt = 0; nt < 4; ++nt)
#pragma unroll
            for (int u = 0; u < 4; ++u) acc[mt][nt][u] = 0.f;

#define LOADSTAGE(s, k0) do {                                   \
        uint32_t d0 = sbase + (s) * STG_BYTES + sOff;           \
        cp16(d0,                  gAh0 + (k0));                 \
        cp16(d0 + 16,             gAh0 + (k0) + 8);             \
        cp16(d0 + STG_A,          gAl0 + (k0));                 \
        cp16(d0 + STG_A + 16,     gAl0 + (k0) + 8);             \
        cp16(d0 + 2 * STG_A,      gBh0 + (k0));                 \
        cp16(d0 + 2 * STG_A + 16, gBh0 + (k0) + 8);             \
        asm volatile("cp.async.commit_group;\n" ::);            \
    } while (0)

    LOADSTAGE(0, 0);
    LOADSTAGE(1, 32);

    int sCur = 0, sNxt = 2;
    for (int kt = 0; kt < 16; ++kt) {
        if (kt < 15)
            asm volatile("cp.async.wait_group 1;\n" ::);
        else
            asm volatile("cp.async.wait_group 0;\n" ::);
        __syncthreads();

        const uint32_t sA0 = sbase + sCur * STG_BYTES + a_off;
        const uint32_t sB0 = sbase + sCur * STG_BYTES + 2 * STG_A + b_off;
#pragma unroll
        for (int ks = 0; ks < 2; ++ks) {
            uint32_t ah[2][4], al[2][4], bh[2][4];
#pragma unroll
            for (int mt = 0; mt < 2; ++mt) {
                uint32_t ad = sA0 + mt * 16 * 80 + ks * 32;
                ldsm4(ah[mt], ad);
                ldsm4(al[mt], ad + STG_A);
            }
#pragma unroll
            for (int ng = 0; ng < 2; ++ng) {
                uint32_t bd = sB0 + ng * 16 * 80 + ks * 32;
                ldsm4(bh[ng], bd);
            }
#pragma unroll
            for (int mt = 0; mt < 2; ++mt)
#pragma unroll
                for (int nt = 0; nt < 4; ++nt) {
                    const int ng = nt >> 1, hb = (nt & 1) * 2;
                    mma_f16(acc[mt][nt], ah[mt], bh[ng][hb], bh[ng][hb + 1]);
                    mma_f16(acc[mt][nt], al[mt], bh[ng][hb], bh[ng][hb + 1]);
                }
        }
        if (kt < 14)
            LOADSTAGE(sNxt, (kt + 2) * 32);
        sCur = (sCur == 2) ? 0 : sCur + 1;
        sNxt = (sNxt == 2) ? 0 : sNxt + 1;
    }
#undef LOADSTAGE

    const int gid = lane >> 2, tig = lane & 3;
#pragma unroll
    for (int mt = 0; mt < 2; ++mt)
#pragma unroll
        for (int nt = 0; nt < 4; ++nt) {
            int row = bm + warp_m * 32 + mt * 16 + gid;
            int col = bn + warp_n * 32 + nt * 8 + tig * 2;
            float b0 = bias[col], b1 = bias[col + 1];
            float r0 = acc[mt][nt][0] + b0;
            float r1 = acc[mt][nt][1] + b1;
            float r2 = acc[mt][nt][2] + b0;
            float r3 = acc[mt][nt][3] + b1;
            if (act) {
                r0 = r0 > 0.f ? r0 : 0.01f * r0;
                r1 = r1 > 0.f ? r1 : 0.01f * r1;
                r2 = r2 > 0.f ? r2 : 0.01f * r2;
                r3 = r3 > 0.f ? r3 : 0.01f * r3;
            }
            if (outF) {
                *(float2*)(outF + (size_t)row * ldc + col)       = make_float2(r0, r1);
                *(float2*)(outF + (size_t)(row + 8) * ldc + col) = make_float2(r2, r3);
            }
            if (outHi) {
                f16 h0, l0, h1, l1, h2, l2, h3, l3;
                split_f16(r0, h0, l0); split_f16(r1, h1, l1);
                split_f16(r2, h2, l2); split_f16(r3, h3, l3);
                __half2 t;
                t.x = h0; t.y = h1;
                *(__half2*)(outHi + (size_t)row * ldc + col) = t;
                t.x = l0; t.y = l1;
                *(__half2*)(outLo + (size_t)row * ldc + col) = t;
                t.x = h2; t.y = h3;
                *(__half2*)(outHi + (size_t)(row + 8) * ldc + col) = t;
                t.x = l2; t.y = l3;
                *(__half2*)(outLo + (size_t)(row + 8) * ldc + col) = t;
            }
        }
}

// ---------------- sparse masked attention v5: TQ=4 + block-staged K tile ----------------
// Per 32-key chunk: stage K[32][512] into smem coalesced (4 wavefronts/LDG vs 32),
// score phase reads smem (row stride 516 floats: conflict-free STS.128 + LDS.128).
#define ATTN_SMEM ((TQ * Dm + 32 * KPAD + Hh * 32 * 4) * 4)   // 78336 bytes

__global__ __launch_bounds__(256, 2) void attn_kernel(
    const float* __restrict__ QKV, const int* __restrict__ seg,
    f16* __restrict__ Oh, f16* __restrict__ Ol) {
    extern __shared__ __align__(16) float sdyn[];
    float* qs   = sdyn;                       // [TQ][Dm]
    float* sK   = sdyn + TQ * Dm;             // [32][KPAD]
    float4* swgt = (float4*)(sK + 32 * KPAD); // [Hh][32]
    __shared__ int sseg[TQ];

    const int i0 = blockIdx.x * TQ;
    const int h = threadIdx.x >> 5;
    const int lane = threadIdx.x & 31;

#pragma unroll
    for (int r = 0; r < TQ; ++r)
        for (int c = threadIdx.x; c < Dm; c += 256)
            qs[r * Dm + c] = QKV[(size_t)(i0 + r) * 1536 + c];
    if (threadIdx.x < TQ) sseg[threadIdx.x] = seg[i0 + threadIdx.x];
    __syncthreads();

    const int s0 = sseg[0], s1 = sseg[1], s2 = sseg[2], s3 = sseg[3];
    const int smin = s0;                     // seg is non-decreasing
    const int nmax = 1 + max(0, (i0 + 3) - smin);

    const float* Kbase = QKV + Dm;
    const float* Vbase = QKV + 2 * Dm;
    const float* qh0 = qs + 0 * Dm + h * DHd;
    const float* qh1 = qs + 1 * Dm + h * DHd;
    const float* qh2 = qs + 2 * Dm + h * DHd;
    const float* qh3 = qs + 3 * Dm + h * DHd;

    float m[TQ], l[TQ];
    float2 acc[TQ];
#pragma unroll
    for (int r = 0; r < TQ; ++r) { m[r] = -1e30f; l[r] = 0.f; acc[r] = make_float2(0.f, 0.f); }
    const float* vcol = Vbase + h * DHd + lane * 2;

    for (int base = 0; base < nmax; base += 32) {
        // ---- stage K chunk: 32 rows x 512 cols, coalesced ----
        __syncthreads();   // previous chunk's smem reads complete before overwrite
        for (int e = threadIdx.x; e < 32 * 128; e += 256) {
            int kk = e >> 7;             // key 0..31
            int c4 = e & 127;            // float4 column
            int tt = base + kk;
            int ttc = tt < nmax ? tt : nmax - 1;
            int jj = (ttc == 0) ? 0 : smin + ttc - 1;
            float4 kv = *(const float4*)(Kbase + (size_t)jj * 1536 + c4 * 4);
            *(float4*)(sK + kk * KPAD + c4 * 4) = kv;
        }
        __syncthreads();

        // ---- scores from smem ----
        int t = base + lane;
        bool inr = t < nmax;
        int j = (t == 0) ? 0 : smin + t - 1;

        const float* kRow = sK + lane * KPAD + h * DHd;
        float d0 = 0.f, d1 = 0.f, d2 = 0.f, d3 = 0.f;
#pragma unroll 8
        for (int c4 = 0; c4 < 16; ++c4) {
            float4 kv = *(const float4*)(kRow + c4 * 4);
            float4 q0 = *(const float4*)(qh0 + c4 * 4);
            float4 q1 = *(const float4*)(qh1 + c4 * 4);
            float4 q2 = *(const float4*)(qh2 + c4 * 4);
            float4 q3 = *(const float4*)(qh3 + c4 * 4);
            d0 += q0.x * kv.x + q0.y * kv.y + q0.z * kv.z + q0.w * kv.w;
            d1 += q1.x * kv.x + q1.y * kv.y + q1.z * kv.z + q1.w * kv.w;
            d2 += q2.x * kv.x + q2.y * kv.y + q2.z * kv.z + q2.w * kv.w;
            d3 += q3.x * kv.x + q3.y * kv.y + q3.z * kv.z + q3.w * kv.w;
        }
        bool k0v = (t == 0);
        float sc[TQ];
        sc[0] = (k0v || (inr && j >= s0 && j < i0 + 0)) ? d0 * 0.125f : -1e30f;
        sc[1] = (k0v || (inr && j >= s1 && j < i0 + 1)) ? d1 * 0.125f : -1e30f;
        sc[2] = (k0v || (inr && j >= s2 && j < i0 + 2)) ? d2 * 0.125f : -1e30f;
        sc[3] = (k0v || (inr && j >= s3 && j < i0 + 3)) ? d3 * 0.125f : -1e30f;

        float4 wv4;
        float* wv = (float*)&wv4;
#pragma unroll
        for (int r = 0; r < TQ; ++r) {
            float cm = sc[r];
#pragma unroll
            for (int off = 16; off; off >>= 1)
                cm = fmaxf(cm, __shfl_xor_sync(0xffffffffu, cm, off));
            float nm = fmaxf(m[r], cm);
            float scale = __expf(m[r] - nm);
            float w = (sc[r] > -1e29f) ? __expf(sc[r] - nm) : 0.f;
            float ws = w;
#pragma unroll
            for (int off = 16; off; off >>= 1)
                ws += __shfl_xor_sync(0xffffffffu, ws, off);
            l[r] = l[r] * scale + ws;
            acc[r].x *= scale; acc[r].y *= scale;
            m[r] = nm;
            wv[r] = w;
        }
        swgt[h * 32 + lane] = wv4;
        __syncwarp();

        // ---- V accumulation (coalesced, shared across 4 rows) ----
        int cnt = min(32, nmax - base);
#pragma unroll 4
        for (int t2 = 0; t2 < cnt; ++t2) {
            int tt2 = base + t2;
            int jj = (tt2 == 0) ? 0 : smin + tt2 - 1;
            float4 ww = swgt[h * 32 + t2];
            float2 v2 = *(const float2*)(vcol + (size_t)jj * 1536);
            acc[0].x += ww.x * v2.x; acc[0].y += ww.x * v2.y;
            acc[1].x += ww.y * v2.x; acc[1].y += ww.y * v2.y;
            acc[2].x += ww.z * v2.x; acc[2].y += ww.z * v2.y;
            acc[3].x += ww.w * v2.x; acc[3].y += ww.w * v2.y;
        }
        __syncwarp();
    }

    const int col = h * DHd + lane * 2;
#pragma unroll
    for (int r = 0; r < TQ; ++r) {
        float inv = 1.f / l[r];
        float ox = acc[r].x * inv;
        float oy = acc[r].y * inv;
        f16 hx, lx, hy, ly;
        split_f16(ox, hx, lx); split_f16(oy, hy, ly);
        __half2 t2o;
        t2o.x = hx; t2o.y = hy;
        *(__half2*)(Oh + (size_t)(i0 + r) * Dm + col) = t2o;
        t2o.x = lx; t2o.y = ly;
        *(__half2*)(Ol + (size_t)(i0 + r) * Dm + col) = t2o;
    }
}

// ---------------- layernorm ----------------
__global__ __launch_bounds__(128) void ln_kernel(
    const float* __restrict__ X, const float* __restrict__ Y,
    const float* __restrict__ g, const float* __restrict__ b,
    float* __restrict__ outF, f16* __restrict__ outHi, f16* __restrict__ outLo) {
    int row = blockIdx.x;
    int tid = threadIdx.x;
    __shared__ float red[4];
    float v[4];
    float s = 0.f;
#pragma unroll
    for (int u = 0; u < 4; ++u) {
        int c = tid + u * 128;
        float t = X[(size_t)row * Dm + c];
        if (Y) t += Y[(size_t)row * Dm + c];
        v[u] = t; s += t;
    }
#pragma unroll
    for (int off = 16; off; off >>= 1) s += __shfl_xor_sync(0xffffffffu, s, off);
    if ((tid & 31) == 0) red[tid >> 5] = s;
    __syncthreads();
    float mean = (red[0] + red[1] + red[2] + red[3]) * (1.f / 512.f);
    float s2 = 0.f;
#pragma unroll
    for (int u = 0; u < 4; ++u) { float d = v[u] - mean; s2 += d * d; }
#pragma unroll
    for (int off = 16; off; off >>= 1) s2 += __shfl_xor_sync(0xffffffffu, s2, off);
    __syncthreads();
    if ((tid & 31) == 0) red[tid >> 5] = s2;
    __syncthreads();
    float var = (red[0] + red[1] + red[2] + red[3]) * (1.f / 512.f);
    float inv = rsqrtf(var + 1e-5f);
#pragma unroll
    for (int u = 0; u < 4; ++u) {
        int c = tid + u * 128;
        float r = (v[u] - mean) * inv * g[c] + b[c];
        if (outF) outF[(size_t)row * Dm + c] = r;
        if (outHi) {
            f16 h, lo2; split_f16(r, h, lo2);
            outHi[(size_t)row * Dm + c] = h;
            outLo[(size_t)row * Dm + c] = lo2;
        }
    }
}

// ---------------- orchestration ----------------
extern "C" void kernel_launch(void* const* d_in, const int* in_sizes, int n_in,
                              void* d_out, int out_size) {
    const int*   idx = (const int*)d_in[0];
    const int*   seq = (const int*)d_in[1];
    const float* Wt  = (const float*)d_in[2];
    const float* bt  = (const float*)d_in[3];
    const float* Wa  = (const float*)d_in[4];
    const float* ba  = (const float*)d_in[5];
    const float* Wm  = (const float*)d_in[6];
    const float* bm  = (const float*)d_in[7];
    const float* sos = (const float*)d_in[8];
    const float* Wq  = (const float*)d_in[9];
    const float* bq  = (const float*)d_in[10];
    const float* Wk  = (const float*)d_in[11];
    const float* bk  = (const float*)d_in[12];
    const float* Wv  = (const float*)d_in[13];
    const float* bv  = (const float*)d_in[14];
    const float* Wo  = (const float*)d_in[15];
    const float* bo  = (const float*)d_in[16];
    const float* W1  = (const float*)d_in[17];
    const float* b1  = (const float*)d_in[18];
    const float* W2  = (const float*)d_in[19];
    const float* b2  = (const float*)d_in[20];
    const float* g1  = (const float*)d_in[21];
    const float* be1 = (const float*)d_in[22];
    const float* g2  = (const float*)d_in[23];
    const float* be2 = (const float*)d_in[24];
    float* out = (float*)d_out;

    float *qkv, *a, *xa, *y, *bqkv, *etab; int* seg;
    f16 *xh, *xl, *oh, *ol, *xah, *xal, *hh, *hl, *Wbh;
    cudaGetSymbolAddress((void**)&qkv, g_qkv);
    cudaGetSymbolAddress((void**)&a,   g_a);
    cudaGetSymbolAddress((void**)&xa,  g_xa);
    cudaGetSymbolAddress((void**)&y,   g_y);
    cudaGetSymbolAddress((void**)&bqkv, g_bqkv);
    cudaGetSymbolAddress((void**)&etab, g_etab);
    cudaGetSymbolAddress((void**)&seg, g_seg);
    cudaGetSymbolAddress((void**)&xh,  g_xh);
    cudaGetSymbolAddress((void**)&xl,  g_xl);
    cudaGetSymbolAddress((void**)&oh,  g_oh);
    cudaGetSymbolAddress((void**)&ol,  g_ol);
    cudaGetSymbolAddress((void**)&xah, g_xah);
    cudaGetSymbolAddress((void**)&xal, g_xal);
    cudaGetSymbolAddress((void**)&hh,  g_hh);
    cudaGetSymbolAddress((void**)&hl,  g_hl);
    cudaGetSymbolAddress((void**)&Wbh, g_Wh);

    cudaFuncSetAttribute(gemm_f16_kernel,
                         cudaFuncAttributeMaxDynamicSharedMemorySize, SMEM_TOT);
    cudaFuncSetAttribute(attn_kernel,
                         cudaFuncAttributeMaxDynamicSharedMemorySize, ATTN_SMEM);

    const size_t WSZ = (size_t)Dm * Dm;

    // launch 1: prep (scan + conv + tables)
    prep_kernel<<<PREP_BLKS, 1024>>>(seq, seg, Wq, Wk, Wv, Wo, W1, W2, Wbh,
                                     Wt, bt, Wa, ba, Wm, bm, bq, bk, bv, etab, bqkv);
    // launch 2: embedding
    embed_kernel<<<L, 128>>>(idx, etab, sos, xh, xl);

    dim3 ggQKV(3 * Dm / 64, L / 64);    // (24, 48)
    dim3 gg(Dm / 64, L / 64);           // (8, 48)
    for (int layer = 0; layer < 2; ++layer) {
        f16* Woh = Wbh + 3 * WSZ;
        f16* W1h = Wbh + 4 * WSZ;
        f16* W2h = Wbh + 5 * WSZ;

        // launch 3: fused QKV GEMM; launch 4 (profiled): attention
        gemm_f16_kernel<<<ggQKV, 128, SMEM_TOT>>>(xh, xl, Wbh, bqkv,
                                                  qkv, nullptr, nullptr, 0, 1536);
        attn_kernel<<<L / TQ, 256, ATTN_SMEM>>>(qkv, seg, oh, ol);
        gemm_f16_kernel<<<gg, 128, SMEM_TOT>>>(oh, ol, Woh, bo,
                                               a, nullptr, nullptr, 0, Dm);
        ln_kernel<<<L, 128>>>(a, nullptr, g1, be1, xa, xah, xal);
        gemm_f16_kernel<<<gg, 128, SMEM_TOT>>>(xah, xal, W1h, b1,
                                               nullptr, hh, hl, 1, Dm);
        gemm_f16_kernel<<<gg, 128, SMEM_TOT>>>(hh, hl, W2h, b2,
                                               y, nullptr, nullptr, 0, Dm);
        if (layer == 0)
            ln_kernel<<<L, 128>>>(xa, y, g2, be2, nullptr, xh, xl);
        else
            ln_kernel<<<L, 128>>>(xa, y, g2, be2, out, nullptr, nullptr);
    }
}